// round 3
// baseline (speedup 1.0000x reference)
#include <cuda_runtime.h>
#include <cstdint>

#define C_CLUST    64
#define NCOPY      16
#define ACC_STRIDE 17                      // 16 dims + 1 count slot
#define ACC_SIZE   (C_CLUST * ACC_STRIDE)  // 1088

// Scratch (no allocations allowed -> __device__ globals)
__device__ float  g_acc[NCOPY][ACC_SIZE];
__device__ float  g_cnt[C_CLUST];
__device__ float  g_invCD[C_CLUST];           // 1 / (C * max(count,1))
__device__ float  g_means[C_CLUST * 16];      // [c][d]
__device__ float  g_meansT[16 * C_CLUST];     // [d][c]
__device__ float  g_var;

__device__ __forceinline__ void red_add_f32(float* addr, float v) {
    asm volatile("red.global.add.f32 [%0], %1;" :: "l"(addr), "f"(v) : "memory");
}

// ---------------------------------------------------------------- zero scratch
__global__ void k_zero() {
    int tid = blockIdx.x * blockDim.x + threadIdx.x;
    int stride = gridDim.x * blockDim.x;
    float* a = (float*)g_acc;
    for (int i = tid; i < NCOPY * ACC_SIZE; i += stride) a[i] = 0.f;
    if (tid == 0) g_var = 0.f;
}

// ---------------------------------------------------------------- pass 1
// Natural layout: lane owns one float4 (point = lane>>2, dim-group g = lane&3)
// and accumulates straight into a per-warp shared acc[64][4] float4 array.
// Intra-warp same-(lab,g) collisions found by one match_any; singletons take a
// plain LDS.128/STS.128 RMW, collision groups (rare) use shared atomicAdd.
__global__ void __launch_bounds__(256) k_pass1(const float4* __restrict__ feat4,
                                               const int* __restrict__ labels,
                                               int npts) {
    __shared__ float4 s_acc[8][C_CLUST][4];
    __shared__ float  s_cnt[8][C_CLUST];

    const int wid  = threadIdx.x >> 5;
    const int lane = threadIdx.x & 31;
    float4 (*acc)[4] = s_acc[wid];
    float*  cnt      = s_cnt[wid];
    {
        float4 z = make_float4(0.f, 0.f, 0.f, 0.f);
        for (int i = lane; i < C_CLUST * 4; i += 32) acc[i >> 2][i & 3] = z;
        for (int i = lane; i < C_CLUST; i += 32) cnt[i] = 0.f;
    }
    __syncwarp();

    const int g     = lane & 3;
    const int gw    = blockIdx.x * 8 + wid;
    const int nwarp = gridDim.x * 8;

    for (int base = gw * 8; base < npts; base += nwarp * 8) {
        __syncwarp();
        int  pt    = base + (lane >> 2);
        bool valid = (pt < npts);
        float4 v   = make_float4(0.f, 0.f, 0.f, 0.f);
        int    lab = 0;
        if (valid) {
            v   = feat4[base * 4 + lane];     // 32 consecutive float4, coalesced
            lab = labels[pt];                 // one 32B sector, warp-broadcast
        }
        // features: dedup writers on (lab, g)
        unsigned key = valid ? (unsigned)(lab * 4 + g) : 256u + lane;
        unsigned mm  = __match_any_sync(0xffffffffu, key);
        if (valid) {
            if (mm == (1u << lane)) {         // fast path: unique address
                float4 o = acc[lab][g];
                o.x += v.x; o.y += v.y; o.z += v.z; o.w += v.w;
                acc[lab][g] = o;
            } else {                          // rare collision: shared atomics
                atomicAdd(&acc[lab][g].x, v.x);
                atomicAdd(&acc[lab][g].y, v.y);
                atomicAdd(&acc[lab][g].z, v.z);
                atomicAdd(&acc[lab][g].w, v.w);
            }
        }
        // counts: dedup on lab among g==0 lanes, leader adds group popcount
        unsigned key2 = (valid && g == 0) ? (unsigned)lab : 512u + lane;
        unsigned m2   = __match_any_sync(0xffffffffu, key2);
        if (valid && g == 0 && (m2 & ((1u << lane) - 1u)) == 0)
            cnt[lab] += (float)__popc(m2);
    }

    // block reduce 8 warp copies -> 1 RED per element per block
    __syncthreads();
    const int copy = blockIdx.x & (NCOPY - 1);
    for (int idx = threadIdx.x; idx < C_CLUST * 16; idx += 256) {
        int c = idx >> 4, d = idx & 15;
        float s = 0.f;
        #pragma unroll
        for (int w = 0; w < 8; w++) s += ((const float*)s_acc[w][c])[d];
        red_add_f32(&g_acc[copy][c * ACC_STRIDE + d], s);
    }
    for (int idx = threadIdx.x; idx < C_CLUST; idx += 256) {
        float s = 0.f;
        #pragma unroll
        for (int w = 0; w < 8; w++) s += s_cnt[w][idx];
        red_add_f32(&g_acc[copy][idx * ACC_STRIDE + 16], s);
    }
}

// ---------------------------------------------------------------- means (1 block, 1024 thr)
__global__ void k_means() {
    __shared__ float s_c[C_CLUST];
    int t = threadIdx.x;
    if (t < C_CLUST) {
        float c = 0.f;
        #pragma unroll
        for (int k = 0; k < NCOPY; k++) c += g_acc[k][t * ACC_STRIDE + 16];
        g_cnt[t] = c;
        float sc = fmaxf(c, 1.f);
        s_c[t] = sc;
        g_invCD[t] = 1.f / ((float)C_CLUST * sc);
    }
    __syncthreads();
    int c = t >> 4, d = t & 15;
    float s = 0.f;
    #pragma unroll
    for (int k = 0; k < NCOPY; k++) s += g_acc[k][c * ACC_STRIDE + d];
    float m = s / s_c[c];
    g_means[c * 16 + d]  = m;
    g_meansT[d * 64 + c] = m;
}

// ---------------------------------------------------------------- pass 2: variance hinge
// var_loss = sum_points hinge(||x - mu + eps|| - 0.5)^2 / (C * count[label])
// Unrolled by 2 to keep two LDG.128 in flight per thread.
__global__ void __launch_bounds__(256) k_pass2(const float4* __restrict__ feat4,
                                               const int* __restrict__ labels,
                                               int n4) {
    __shared__ float s_mT[16][C_CLUST + 1];   // pad -> low conflicts
    __shared__ float s_inv[C_CLUST];
    __shared__ float s_w[8];

    for (int i = threadIdx.x; i < 16 * C_CLUST; i += 256)
        s_mT[i >> 6][i & 63] = g_meansT[i];
    if (threadIdx.x < C_CLUST) s_inv[threadIdx.x] = g_invCD[threadIdx.x];
    __syncthreads();

    const int lane = threadIdx.x & 31;
    const int g    = threadIdx.x & 3;
    const int d0   = g * 4;
    const int stride = gridDim.x * 512;
    float local = 0.f;

    for (int j = blockIdx.x * 512 + threadIdx.x; j - lane < n4; j += stride) {
        int  jb = j + 256;
        bool a1 = (j < n4), a2 = (jb < n4);
        float4 v1, v2;
        int l1 = 0, l2 = 0;
        if (a1) { l1 = labels[j  >> 2]; v1 = feat4[j];  }
        if (a2) { l2 = labels[jb >> 2]; v2 = feat4[jb]; }

        float p1 = 0.f, p2 = 0.f;
        if (a1) {
            float dx = v1.x - s_mT[d0 + 0][l1] + 1e-8f;
            float dy = v1.y - s_mT[d0 + 1][l1] + 1e-8f;
            float dz = v1.z - s_mT[d0 + 2][l1] + 1e-8f;
            float dw = v1.w - s_mT[d0 + 3][l1] + 1e-8f;
            p1 = fmaf(dx, dx, fmaf(dy, dy, fmaf(dz, dz, dw * dw)));
        }
        if (a2) {
            float dx = v2.x - s_mT[d0 + 0][l2] + 1e-8f;
            float dy = v2.y - s_mT[d0 + 1][l2] + 1e-8f;
            float dz = v2.z - s_mT[d0 + 2][l2] + 1e-8f;
            float dw = v2.w - s_mT[d0 + 3][l2] + 1e-8f;
            p2 = fmaf(dx, dx, fmaf(dy, dy, fmaf(dz, dz, dw * dw)));
        }
        p1 += __shfl_xor_sync(0xffffffffu, p1, 1);
        p1 += __shfl_xor_sync(0xffffffffu, p1, 2);
        p2 += __shfl_xor_sync(0xffffffffu, p2, 1);
        p2 += __shfl_xor_sync(0xffffffffu, p2, 2);
        if (g == 0) {
            if (a1) {
                float h = fmaxf(sqrtf(p1) - 0.5f, 0.f);
                local += h * h * s_inv[l1];
            }
            if (a2) {
                float h = fmaxf(sqrtf(p2) - 0.5f, 0.f);
                local += h * h * s_inv[l2];
            }
        }
    }

    #pragma unroll
    for (int o = 16; o > 0; o >>= 1)
        local += __shfl_xor_sync(0xffffffffu, local, o);
    if (lane == 0) s_w[threadIdx.x >> 5] = local;
    __syncthreads();
    if (threadIdx.x == 0) {
        float s = 0.f;
        #pragma unroll
        for (int w = 0; w < 8; w++) s += s_w[w];
        red_add_f32(&g_var, s);
    }
}

// ---------------------------------------------------------------- finalize (1 block, 256 thr)
__global__ void k_final(float* __restrict__ out) {
    __shared__ float s_m[C_CLUST][16];
    __shared__ float s_red[256];
    int t = threadIdx.x;
    for (int i = t; i < C_CLUST * 16; i += 256)
        ((float*)s_m)[i] = g_means[i];
    __syncthreads();

    float regp = 0.f;
    if (t < C_CLUST) {
        float s = 0.f;
        #pragma unroll
        for (int d = 0; d < 16; d++) {
            float v = s_m[t][d] + 1e-8f;
            s += v * v;
        }
        regp = sqrtf(s);
    }

    float dl = 0.f;
    for (int p = t; p < C_CLUST * C_CLUST; p += 256) {
        int i = p >> 6, jj = p & 63;
        if (i != jj) {
            float s = 0.f;
            #pragma unroll
            for (int d = 0; d < 16; d++) {
                float df = s_m[i][d] - s_m[jj][d] + 1e-8f;
                s += df * df;
            }
            float pd = sqrtf(s);
            float h = fmaxf(3.0f - pd, 0.f);   // 2 * DELTA_DIST
            dl += h * h;
        }
    }

    s_red[t] = dl; __syncthreads();
    for (int o = 128; o > 0; o >>= 1) { if (t < o) s_red[t] += s_red[t + o]; __syncthreads(); }
    float dist_loss = s_red[0] / (float)(C_CLUST * (C_CLUST - 1));
    __syncthreads();

    s_red[t] = regp; __syncthreads();
    for (int o = 128; o > 0; o >>= 1) { if (t < o) s_red[t] += s_red[t + o]; __syncthreads(); }
    float reg_loss = s_red[0] / (float)C_CLUST;

    if (t == 0) {
        float var_loss = g_var;
        out[0] = var_loss + dist_loss + 0.001f * reg_loss;
        out[1] = var_loss;
        out[2] = dist_loss;
        out[3] = reg_loss;
    }
}

// ---------------------------------------------------------------- launch
extern "C" void kernel_launch(void* const* d_in, const int* in_sizes, int n_in,
                              void* d_out, int out_size) {
    const float4* feat4  = (const float4*)d_in[0];
    const int*    labels = (const int*)d_in[1];
    int N  = in_sizes[1];     // number of points
    int n4 = N * 4;           // float4 count (D=16)

    k_zero <<<68, 256>>>();
    k_pass1<<<148 * 8, 256>>>(feat4, labels, N);
    k_means<<<1, 1024>>>();
    k_pass2<<<148 * 8, 256>>>(feat4, labels, n4);
    k_final<<<1, 256>>>((float*)d_out);
}